// round 2
// baseline (speedup 1.0000x reference)
#include <cuda_runtime.h>
#include <math.h>

// Problem constants (fixed by the dataset)
static constexpr int SQ = 2048;     // sequence length (S == F)
static constexpr int DM = 1024;     // d_model
static constexpr int NH = 16;       // heads
static constexpr long long SS = (long long)SQ * SQ;

// ---------------- scratch (static device globals; no allocs allowed) -------
__device__ float g_rel [SQ * DM];          // positional encoding (reversed)
__device__ float g_q   [SQ * DM];
__device__ float g_k   [SQ * DM];
__device__ float g_v   [SQ * DM];
__device__ float g_qu  [SQ * DM];          // q + u_param
__device__ float g_qv  [SQ * DM];          // q + v_param
__device__ float g_qrel[SQ * DM];          // rel_enc @ Wkr^T
__device__ float g_bhat[(long long)NH * SQ * SQ];   // 256 MB: B_D_hat per head
__device__ float g_ctx [SQ * DM];          // attn @ v assembled
__device__ unsigned int g_headmax[NH];

// ---------------- small kernels --------------------------------------------
__global__ void init_kernel() {
    if (threadIdx.x < NH) g_headmax[threadIdx.x] = 0u;
}

// rel_enc = pos_encoding(S, D)[::-1]; computed in double for the transcendental,
// but the angle is rounded through fp32 exactly as the reference does.
__global__ void relenc_kernel() {
    int idx = blockIdx.x * blockDim.x + threadIdx.x;
    if (idx >= SQ * DM) return;
    int f = idx >> 10;          // / DM
    int c = idx & (DM - 1);
    int p = SQ - 1 - f;         // reversed position
    int i2 = c & ~1;
    double dv = exp(-((double)i2 / (double)DM) * log(10000.0));
    float divf = (float)dv;
    float angf = (float)p * divf;
    double a = (double)angf;
    g_rel[idx] = (float)((c & 1) ? cos(a) : sin(a));
}

__global__ void addbias_kernel(const float* __restrict__ u,
                               const float* __restrict__ v) {
    int idx = blockIdx.x * blockDim.x + threadIdx.x;
    if (idx >= SQ * DM) return;
    int c = idx & (DM - 1);   // u/v are (H*dh) = DM contiguous
    float q = g_q[idx];
    g_qu[idx] = q + u[c];
    g_qv[idx] = q + v[c];
}

// ---------------- tiled fp32 GEMM core: C = A(MxK) * B(NxK)^T ---------------
// BM=BN=128, BK=16, 256 threads, 8x8 micro-tile per thread.
// All shapes used here are exact multiples of the tiles (no bounds checks).
__device__ __forceinline__ void gemm_tn_core(
    const float* __restrict__ A, const float* __restrict__ B,
    int K, int lda, int ldb, int m0, int n0,
    float (&As)[16][128], float (&Bs)[16][128], float (&acc)[8][8])
{
    const int t  = threadIdx.x;
    const int ar = t >> 2;            // 0..63
    const int ak = (t & 3) << 2;      // 0,4,8,12
    const int tx = t & 15;
    const int ty = t >> 4;
    for (int k0 = 0; k0 < K; k0 += 16) {
        #pragma unroll
        for (int i = 0; i < 2; i++) {
            int m = ar + (i << 6);
            float4 av = *(const float4*)(A + (long long)(m0 + m) * lda + (k0 + ak));
            As[ak + 0][m] = av.x; As[ak + 1][m] = av.y;
            As[ak + 2][m] = av.z; As[ak + 3][m] = av.w;
            float4 bv = *(const float4*)(B + (long long)(n0 + m) * ldb + (k0 + ak));
            Bs[ak + 0][m] = bv.x; Bs[ak + 1][m] = bv.y;
            Bs[ak + 2][m] = bv.z; Bs[ak + 3][m] = bv.w;
        }
        __syncthreads();
        #pragma unroll
        for (int kk = 0; kk < 16; kk++) {
            float a[8], b[8];
            *(float4*)(a)     = *(const float4*)&As[kk][ty * 8];
            *(float4*)(a + 4) = *(const float4*)&As[kk][ty * 8 + 4];
            *(float4*)(b)     = *(const float4*)&Bs[kk][tx * 8];
            *(float4*)(b + 4) = *(const float4*)&Bs[kk][tx * 8 + 4];
            #pragma unroll
            for (int i = 0; i < 8; i++)
                #pragma unroll
                for (int j = 0; j < 8; j++)
                    acc[i][j] = fmaf(a[i], b[j], acc[i][j]);
        }
        __syncthreads();
    }
}

// Generic batched TN GEMM (used for projections and for B_D_hat).
__global__ void __launch_bounds__(256) sgemm_tn_kernel(
    const float* __restrict__ A, const float* __restrict__ B, float* __restrict__ C,
    int K, int lda, int ldb, int ldc,
    long long aZ, long long bZ, long long cZ)
{
    __shared__ float As[16][128], Bs[16][128];
    A += (long long)blockIdx.z * aZ;
    B += (long long)blockIdx.z * bZ;
    C += (long long)blockIdx.z * cZ;
    int m0 = blockIdx.y * 128, n0 = blockIdx.x * 128;
    float acc[8][8] = {};
    gemm_tn_core(A, B, K, lda, ldb, m0, n0, As, Bs, acc);
    int tx = threadIdx.x & 15, ty = threadIdx.x >> 4;
    #pragma unroll
    for (int i = 0; i < 8; i++) {
        float* cr = C + (long long)(m0 + ty * 8 + i) * ldc + n0 + tx * 8;
        *(float4*)cr       = make_float4(acc[i][0], acc[i][1], acc[i][2], acc[i][3]);
        *(float4*)(cr + 4) = make_float4(acc[i][4], acc[i][5], acc[i][6], acc[i][7]);
    }
}

// Score: A_C = (q+u)_h @ k_h^T, add rel-shifted B_D (gathered from g_bhat),
// scale by 1/sqrt(D), add mask; write pre-softmax scores into the weights region.
__global__ void __launch_bounds__(256) score_kernel(
    const float* __restrict__ mask, float* __restrict__ W)
{
    __shared__ float As[16][128], Bs[16][128];
    int h = blockIdx.z;
    const float* A  = g_qu + h * 64;
    const float* B  = g_k  + h * 64;
    const float* bh = g_bhat + (long long)h * SS;
    float* C = W + (long long)h * SS;
    int m0 = blockIdx.y * 128, n0 = blockIdx.x * 128;
    float acc[8][8] = {};
    gemm_tn_core(A, B, 64, DM, DM, m0, n0, As, Bs, acc);
    int tx = threadIdx.x & 15, ty = threadIdx.x >> 4;
    #pragma unroll
    for (int i = 0; i < 8; i++) {
        int s = m0 + ty * 8 + i;
        #pragma unroll
        for (int j = 0; j < 8; j++) {
            int f = n0 + tx * 8 + j;
            // exact _rel_enc_shift gather: pad to (S, S+1), flatten,
            // slice starting at S-1.
            long long flat = (long long)s * SQ + f + (SQ - 1);
            int sp = (int)(flat / (SQ + 1));
            int fp = (int)(flat - (long long)sp * (SQ + 1));
            float bd = (fp == SQ) ? 0.0f : bh[(long long)sp * SQ + fp];
            long long o = (long long)s * SQ + f;
            C[o] = (acc[i][j] + bd) * 0.03125f + mask[o];   // 1/sqrt(1024)
        }
    }
}

// Row softmax in place over W (16 x 2048 rows of 2048). Per-row max weight is
// 1/sum_exp (softmax is monotone); per-head max tracked via atomicMax on bits.
__global__ void __launch_bounds__(256) softmax_kernel(float* __restrict__ W)
{
    int s = blockIdx.x, h = blockIdx.y;
    float* row = W + ((long long)h * SQ + s) * SQ;
    int t = threadIdx.x;
    float4 v0 = *(float4*)(row + t * 8);
    float4 v1 = *(float4*)(row + t * 8 + 4);
    float vm = fmaxf(fmaxf(fmaxf(v0.x, v0.y), fmaxf(v0.z, v0.w)),
                     fmaxf(fmaxf(v1.x, v1.y), fmaxf(v1.z, v1.w)));
    __shared__ float red[8];
    int lane = t & 31, wid = t >> 5;
    #pragma unroll
    for (int o = 16; o > 0; o >>= 1) vm = fmaxf(vm, __shfl_xor_sync(0xffffffffu, vm, o));
    if (lane == 0) red[wid] = vm;
    __syncthreads();
    float M = red[0];
    #pragma unroll
    for (int i = 1; i < 8; i++) M = fmaxf(M, red[i]);
    __syncthreads();
    float e[8];
    e[0] = __expf(v0.x - M); e[1] = __expf(v0.y - M);
    e[2] = __expf(v0.z - M); e[3] = __expf(v0.w - M);
    e[4] = __expf(v1.x - M); e[5] = __expf(v1.y - M);
    e[6] = __expf(v1.z - M); e[7] = __expf(v1.w - M);
    float sum = ((e[0] + e[1]) + (e[2] + e[3])) + ((e[4] + e[5]) + (e[6] + e[7]));
    #pragma unroll
    for (int o = 16; o > 0; o >>= 1) sum += __shfl_xor_sync(0xffffffffu, sum, o);
    if (lane == 0) red[wid] = sum;
    __syncthreads();
    float T = red[0];
    #pragma unroll
    for (int i = 1; i < 8; i++) T += red[i];
    float inv = 1.0f / T;
    *(float4*)(row + t * 8)     = make_float4(e[0] * inv, e[1] * inv, e[2] * inv, e[3] * inv);
    *(float4*)(row + t * 8 + 4) = make_float4(e[4] * inv, e[5] * inv, e[6] * inv, e[7] * inv);
    if (t == 0) atomicMax(&g_headmax[h], __float_as_uint(inv));  // max weight of row == 1/T
}

__global__ void loss_kernel(float* __restrict__ loss) {
    if (threadIdx.x == 0) {
        float s = 0.0f;
        #pragma unroll
        for (int h = 0; h < NH; h++) s += __uint_as_float(g_headmax[h]);
        loss[0] = s / (float)NH;
    }
}

// attn @ v per head: O[m, hd] = sum_f W[h][m][f] * v[f, h*64+d]. NN GEMM,
// BM=128, BN=64 (full head dim), BK=16, 256 threads, 8x4 micro-tile.
__global__ void __launch_bounds__(256) av_kernel(const float* __restrict__ W)
{
    __shared__ float As[16][128];
    __shared__ float Bs[16][64];
    int h = blockIdx.z;
    const float* A = W + (long long)h * SS;    // [SQ, SQ]
    const float* B = g_v + h * 64;             // [SQ, 64], ld = DM
    float* C = g_ctx + h * 64;                 // ld = DM
    int m0 = blockIdx.y * 128;
    int t = threadIdx.x;
    int ar = t >> 2, ak = (t & 3) << 2;
    int brow = t >> 4, bcol = (t & 15) << 2;
    int tx = t & 15, ty = t >> 4;
    float acc[8][4] = {};
    for (int k0 = 0; k0 < SQ; k0 += 16) {
        #pragma unroll
        for (int i = 0; i < 2; i++) {
            int m = ar + (i << 6);
            float4 av = *(const float4*)(A + (long long)(m0 + m) * SQ + k0 + ak);
            As[ak + 0][m] = av.x; As[ak + 1][m] = av.y;
            As[ak + 2][m] = av.z; As[ak + 3][m] = av.w;
        }
        float4 bv = *(const float4*)(B + (long long)(k0 + brow) * DM + bcol);
        *(float4*)&Bs[brow][bcol] = bv;
        __syncthreads();
        #pragma unroll
        for (int kk = 0; kk < 16; kk++) {
            float a[8], b[4];
            *(float4*)(a)     = *(const float4*)&As[kk][ty * 8];
            *(float4*)(a + 4) = *(const float4*)&As[kk][ty * 8 + 4];
            *(float4*)(b)     = *(const float4*)&Bs[kk][tx * 4];
            #pragma unroll
            for (int i = 0; i < 8; i++)
                #pragma unroll
                for (int j = 0; j < 4; j++)
                    acc[i][j] = fmaf(a[i], b[j], acc[i][j]);
        }
        __syncthreads();
    }
    #pragma unroll
    for (int i = 0; i < 8; i++) {
        float* cr = C + (long long)(m0 + ty * 8 + i) * DM + tx * 4;
        *(float4*)cr = make_float4(acc[i][0], acc[i][1], acc[i][2], acc[i][3]);
    }
}

// out = gelu(ctx @ Wf^T), exact gelu.
__global__ void __launch_bounds__(256) final_kernel(
    const float* __restrict__ Wf, float* __restrict__ out)
{
    __shared__ float As[16][128], Bs[16][128];
    int m0 = blockIdx.y * 128, n0 = blockIdx.x * 128;
    float acc[8][8] = {};
    gemm_tn_core(g_ctx, Wf, DM, DM, DM, m0, n0, As, Bs, acc);
    int tx = threadIdx.x & 15, ty = threadIdx.x >> 4;
    #pragma unroll
    for (int i = 0; i < 8; i++) {
        float r[8];
        #pragma unroll
        for (int j = 0; j < 8; j++) {
            float x = acc[i][j];
            r[j] = 0.5f * x * (1.0f + erff(x * 0.70710678118654752f));
        }
        float* cr = out + (long long)(m0 + ty * 8 + i) * DM + n0 + tx * 8;
        *(float4*)cr       = make_float4(r[0], r[1], r[2], r[3]);
        *(float4*)(cr + 4) = make_float4(r[4], r[5], r[6], r[7]);
    }
}

// ---------------- launch ----------------------------------------------------
extern "C" void kernel_launch(void* const* d_in, const int* in_sizes, int n_in,
                              void* d_out, int out_size)
{
    const float* query = (const float*)d_in[0];
    const float* key   = (const float*)d_in[1];
    const float* value = (const float*)d_in[2];
    const float* mask  = (const float*)d_in[3];
    const float* Wq    = (const float*)d_in[4];
    const float* Wke   = (const float*)d_in[5];
    const float* Wkr   = (const float*)d_in[6];
    const float* Wv    = (const float*)d_in[7];
    const float* Wf    = (const float*)d_in[8];
    const float* u_p   = (const float*)d_in[9];
    const float* v_p   = (const float*)d_in[10];

    float* out  = (float*)d_out;                       // (1,2048,1024)
    float* Wt   = out + (long long)SQ * DM;            // (1,16,2048,2048)
    float* loss = Wt + (long long)NH * SS;             // scalar

    float *fq, *fk, *fv, *frel, *fqrel, *fqv, *fbhat;
    cudaGetSymbolAddress((void**)&fq,    g_q);
    cudaGetSymbolAddress((void**)&fk,    g_k);
    cudaGetSymbolAddress((void**)&fv,    g_v);
    cudaGetSymbolAddress((void**)&frel,  g_rel);
    cudaGetSymbolAddress((void**)&fqrel, g_qrel);
    cudaGetSymbolAddress((void**)&fqv,   g_qv);
    cudaGetSymbolAddress((void**)&fbhat, g_bhat);

    init_kernel<<<1, 32>>>();
    relenc_kernel<<<(SQ * DM) / 256, 256>>>();

    dim3 gP(DM / 128, SQ / 128);
    sgemm_tn_kernel<<<gP, 256>>>(query, Wq,  fq,    DM, DM, DM, DM, 0, 0, 0);
    sgemm_tn_kernel<<<gP, 256>>>(key,   Wke, fk,    DM, DM, DM, DM, 0, 0, 0);
    sgemm_tn_kernel<<<gP, 256>>>(value, Wv,  fv,    DM, DM, DM, DM, 0, 0, 0);
    sgemm_tn_kernel<<<gP, 256>>>(frel,  Wkr, fqrel, DM, DM, DM, DM, 0, 0, 0);

    addbias_kernel<<<(SQ * DM) / 256, 256>>>(u_p, v_p);

    dim3 gB(SQ / 128, SQ / 128, NH);
    // B_D_hat[h] = (q+v)_h @ (rel_enc @ Wkr^T)_h^T
    sgemm_tn_kernel<<<gB, 256>>>(fqv, fqrel, fbhat, 64, DM, DM, SQ, 64, 64, SS);
    score_kernel<<<gB, 256>>>(mask, Wt);
    softmax_kernel<<<dim3(SQ, NH), 256>>>(Wt);
    loss_kernel<<<1, 32>>>(loss);
    av_kernel<<<dim3(1, SQ / 128, NH), 256>>>(Wt);

    dim3 gF(DM / 128, SQ / 128);
    final_kernel<<<gF, 256>>>(Wf, out);
}

// round 3
// speedup vs baseline: 1.5872x; 1.5872x over previous
#include <cuda_runtime.h>
#include <math.h>

// Problem constants (fixed by the dataset)
static constexpr int SQ = 2048;     // sequence length (S == F)
static constexpr int DM = 1024;     // d_model
static constexpr int NH = 16;       // heads
static constexpr long long SS = (long long)SQ * SQ;

// ---------------- scratch (static device globals; no allocs allowed) -------
__device__ float g_rel [SQ * DM];          // positional encoding (reversed)
__device__ float g_q   [SQ * DM];
__device__ float g_k   [SQ * DM];
__device__ float g_v   [SQ * DM];
__device__ float g_qu  [SQ * DM];          // q + u_param
__device__ float g_qv  [SQ * DM];          // q + v_param
__device__ float g_qrel[SQ * DM];          // rel_enc @ Wkr^T
__device__ float g_bhat[(long long)NH * SQ * SQ];   // 256 MB: B_D_hat per head
__device__ float g_ctx [SQ * DM];          // attn @ v assembled
__device__ unsigned int g_headmax[NH];

// ---------------- small kernels --------------------------------------------
__global__ void init_kernel() {
    if (threadIdx.x < NH) g_headmax[threadIdx.x] = 0u;
}

// rel_enc = pos_encoding(S, D)[::-1]; computed in double for the transcendental,
// but the angle is rounded through fp32 exactly as the reference does.
__global__ void relenc_kernel() {
    int idx = blockIdx.x * blockDim.x + threadIdx.x;
    if (idx >= SQ * DM) return;
    int f = idx >> 10;          // / DM
    int c = idx & (DM - 1);
    int p = SQ - 1 - f;         // reversed position
    int i2 = c & ~1;
    double dv = exp(-((double)i2 / (double)DM) * log(10000.0));
    float divf = (float)dv;
    float angf = (float)p * divf;
    double a = (double)angf;
    g_rel[idx] = (float)((c & 1) ? cos(a) : sin(a));
}

__global__ void addbias_kernel(const float* __restrict__ u,
                               const float* __restrict__ v) {
    int idx = blockIdx.x * blockDim.x + threadIdx.x;
    if (idx >= SQ * DM) return;
    int c = idx & (DM - 1);   // u/v are (H*dh) = DM contiguous
    float q = g_q[idx];
    g_qu[idx] = q + u[c];
    g_qv[idx] = q + v[c];
}

// ---------------- tiled fp32 GEMM core: C = A(MxK) * B(NxK)^T ---------------
// BM=BN=128, BK=16, 256 threads, 8x8 micro-tile per thread.
// All shapes used here are exact multiples of the tiles (no bounds checks).
__device__ __forceinline__ void gemm_tn_core(
    const float* __restrict__ A, const float* __restrict__ B,
    int K, int lda, int ldb, int m0, int n0,
    float (&As)[16][128], float (&Bs)[16][128], float (&acc)[8][8])
{
    const int t  = threadIdx.x;
    const int ar = t >> 2;            // 0..63
    const int ak = (t & 3) << 2;      // 0,4,8,12
    const int tx = t & 15;
    const int ty = t >> 4;
    for (int k0 = 0; k0 < K; k0 += 16) {
        #pragma unroll
        for (int i = 0; i < 2; i++) {
            int m = ar + (i << 6);
            float4 av = *(const float4*)(A + (long long)(m0 + m) * lda + (k0 + ak));
            As[ak + 0][m] = av.x; As[ak + 1][m] = av.y;
            As[ak + 2][m] = av.z; As[ak + 3][m] = av.w;
            float4 bv = *(const float4*)(B + (long long)(n0 + m) * ldb + (k0 + ak));
            Bs[ak + 0][m] = bv.x; Bs[ak + 1][m] = bv.y;
            Bs[ak + 2][m] = bv.z; Bs[ak + 3][m] = bv.w;
        }
        __syncthreads();
        #pragma unroll
        for (int kk = 0; kk < 16; kk++) {
            float a[8], b[8];
            *(float4*)(a)     = *(const float4*)&As[kk][ty * 8];
            *(float4*)(a + 4) = *(const float4*)&As[kk][ty * 8 + 4];
            *(float4*)(b)     = *(const float4*)&Bs[kk][tx * 8];
            *(float4*)(b + 4) = *(const float4*)&Bs[kk][tx * 8 + 4];
            #pragma unroll
            for (int i = 0; i < 8; i++)
                #pragma unroll
                for (int j = 0; j < 8; j++)
                    acc[i][j] = fmaf(a[i], b[j], acc[i][j]);
        }
        __syncthreads();
    }
}

// Generic batched TN GEMM (used for projections and for B_D_hat).
__global__ void __launch_bounds__(256) sgemm_tn_kernel(
    const float* __restrict__ A, const float* __restrict__ B, float* __restrict__ C,
    int K, int lda, int ldb, int ldc,
    long long aZ, long long bZ, long long cZ)
{
    __shared__ float As[16][128], Bs[16][128];
    A += (long long)blockIdx.z * aZ;
    B += (long long)blockIdx.z * bZ;
    C += (long long)blockIdx.z * cZ;
    int m0 = blockIdx.y * 128, n0 = blockIdx.x * 128;
    float acc[8][8] = {};
    gemm_tn_core(A, B, K, lda, ldb, m0, n0, As, Bs, acc);
    int tx = threadIdx.x & 15, ty = threadIdx.x >> 4;
    #pragma unroll
    for (int i = 0; i < 8; i++) {
        float* cr = C + (long long)(m0 + ty * 8 + i) * ldc + n0 + tx * 8;
        *(float4*)cr       = make_float4(acc[i][0], acc[i][1], acc[i][2], acc[i][3]);
        *(float4*)(cr + 4) = make_float4(acc[i][4], acc[i][5], acc[i][6], acc[i][7]);
    }
}

// Score: A_C = (q+u)_h @ k_h^T, add rel-shifted B_D (gathered from g_bhat),
// scale by 1/sqrt(D), add mask; write pre-softmax scores into the weights region.
__global__ void __launch_bounds__(256) score_kernel(
    const float* __restrict__ mask, float* __restrict__ W)
{
    __shared__ float As[16][128], Bs[16][128];
    int h = blockIdx.z;
    const float* A  = g_qu + h * 64;
    const float* B  = g_k  + h * 64;
    const float* bh = g_bhat + (long long)h * SS;
    float* C = W + (long long)h * SS;
    int m0 = blockIdx.y * 128, n0 = blockIdx.x * 128;
    float acc[8][8] = {};
    gemm_tn_core(A, B, 64, DM, DM, m0, n0, As, Bs, acc);
    int tx = threadIdx.x & 15, ty = threadIdx.x >> 4;
    #pragma unroll
    for (int i = 0; i < 8; i++) {
        int s = m0 + ty * 8 + i;
        #pragma unroll
        for (int j = 0; j < 8; j++) {
            int f = n0 + tx * 8 + j;
            // exact _rel_enc_shift gather: pad to (S, S+1), flatten,
            // slice starting at S-1.
            long long flat = (long long)s * SQ + f + (SQ - 1);
            int sp = (int)(flat / (SQ + 1));
            int fp = (int)(flat - (long long)sp * (SQ + 1));
            float bd = (fp == SQ) ? 0.0f : bh[(long long)sp * SQ + fp];
            long long o = (long long)s * SQ + f;
            C[o] = (acc[i][j] + bd) * 0.03125f + mask[o];   // 1/sqrt(1024)
        }
    }
}

// Row softmax in place over W (16 x 2048 rows of 2048). Per-row max weight is
// 1/sum_exp (softmax is monotone); per-head max tracked via atomicMax on bits.
__global__ void __launch_bounds__(256) softmax_kernel(float* __restrict__ W)
{
    int s = blockIdx.x, h = blockIdx.y;
    float* row = W + ((long long)h * SQ + s) * SQ;
    int t = threadIdx.x;
    float4 v0 = *(float4*)(row + t * 8);
    float4 v1 = *(float4*)(row + t * 8 + 4);
    float vm = fmaxf(fmaxf(fmaxf(v0.x, v0.y), fmaxf(v0.z, v0.w)),
                     fmaxf(fmaxf(v1.x, v1.y), fmaxf(v1.z, v1.w)));
    __shared__ float red[8];
    int lane = t & 31, wid = t >> 5;
    #pragma unroll
    for (int o = 16; o > 0; o >>= 1) vm = fmaxf(vm, __shfl_xor_sync(0xffffffffu, vm, o));
    if (lane == 0) red[wid] = vm;
    __syncthreads();
    float M = red[0];
    #pragma unroll
    for (int i = 1; i < 8; i++) M = fmaxf(M, red[i]);
    __syncthreads();
    float e[8];
    e[0] = __expf(v0.x - M); e[1] = __expf(v0.y - M);
    e[2] = __expf(v0.z - M); e[3] = __expf(v0.w - M);
    e[4] = __expf(v1.x - M); e[5] = __expf(v1.y - M);
    e[6] = __expf(v1.z - M); e[7] = __expf(v1.w - M);
    float sum = ((e[0] + e[1]) + (e[2] + e[3])) + ((e[4] + e[5]) + (e[6] + e[7]));
    #pragma unroll
    for (int o = 16; o > 0; o >>= 1) sum += __shfl_xor_sync(0xffffffffu, sum, o);
    if (lane == 0) red[wid] = sum;
    __syncthreads();
    float T = red[0];
    #pragma unroll
    for (int i = 1; i < 8; i++) T += red[i];
    float inv = 1.0f / T;
    *(float4*)(row + t * 8)     = make_float4(e[0] * inv, e[1] * inv, e[2] * inv, e[3] * inv);
    *(float4*)(row + t * 8 + 4) = make_float4(e[4] * inv, e[5] * inv, e[6] * inv, e[7] * inv);
    if (t == 0) atomicMax(&g_headmax[h], __float_as_uint(inv));  // max weight of row == 1/T
}

__global__ void loss_kernel(float* __restrict__ loss) {
    if (threadIdx.x == 0) {
        float s = 0.0f;
        #pragma unroll
        for (int h = 0; h < NH; h++) s += __uint_as_float(g_headmax[h]);
        loss[0] = s / (float)NH;
    }
}

// attn @ v per head: O[m, hd] = sum_f W[h][m][f] * v[f, h*64+d]. NN GEMM,
// BM=128, BN=64 (full head dim), BK=16, 256 threads, 8x4 micro-tile.
__global__ void __launch_bounds__(256) av_kernel(const float* __restrict__ W)
{
    __shared__ float As[16][128];
    __shared__ float Bs[16][64];
    int h = blockIdx.z;
    const float* A = W + (long long)h * SS;    // [SQ, SQ]
    const float* B = g_v + h * 64;             // [SQ, 64], ld = DM
    float* C = g_ctx + h * 64;                 // ld = DM
    int m0 = blockIdx.y * 128;
    int t = threadIdx.x;
    int ar = t >> 2, ak = (t & 3) << 2;
    int brow = t >> 4, bcol = (t & 15) << 2;
    int tx = t & 15, ty = t >> 4;
    float acc[8][4] = {};
    for (int k0 = 0; k0 < SQ; k0 += 16) {
        #pragma unroll
        for (int i = 0; i < 2; i++) {
            int m = ar + (i << 6);
            float4 av = *(const float4*)(A + (long long)(m0 + m) * SQ + k0 + ak);
            As[ak + 0][m] = av.x; As[ak + 1][m] = av.y;
            As[ak + 2][m] = av.z; As[ak + 3][m] = av.w;
        }
        float4 bv = *(const float4*)(B + (long long)(k0 + brow) * DM + bcol);
        *(float4*)&Bs[brow][bcol] = bv;
        __syncthreads();
        #pragma unroll
        for (int kk = 0; kk < 16; kk++) {
            float a[8], b[4];
            *(float4*)(a)     = *(const float4*)&As[kk][ty * 8];
            *(float4*)(a + 4) = *(const float4*)&As[kk][ty * 8 + 4];
            *(float4*)(b)     = *(const float4*)&Bs[kk][tx * 4];
            #pragma unroll
            for (int i = 0; i < 8; i++)
                #pragma unroll
                for (int j = 0; j < 4; j++)
                    acc[i][j] = fmaf(a[i], b[j], acc[i][j]);
        }
        __syncthreads();
    }
    #pragma unroll
    for (int i = 0; i < 8; i++) {
        float* cr = C + (long long)(m0 + ty * 8 + i) * DM + tx * 4;
        *(float4*)cr = make_float4(acc[i][0], acc[i][1], acc[i][2], acc[i][3]);
    }
}

// out = gelu(ctx @ Wf^T), exact gelu.
__global__ void __launch_bounds__(256) final_kernel(
    const float* __restrict__ Wf, float* __restrict__ out)
{
    __shared__ float As[16][128], Bs[16][128];
    int m0 = blockIdx.y * 128, n0 = blockIdx.x * 128;
    float acc[8][8] = {};
    gemm_tn_core(g_ctx, Wf, DM, DM, DM, m0, n0, As, Bs, acc);
    int tx = threadIdx.x & 15, ty = threadIdx.x >> 4;
    #pragma unroll
    for (int i = 0; i < 8; i++) {
        float r[8];
        #pragma unroll
        for (int j = 0; j < 8; j++) {
            float x = acc[i][j];
            r[j] = 0.5f * x * (1.0f + erff(x * 0.70710678118654752f));
        }
        float* cr = out + (long long)(m0 + ty * 8 + i) * DM + n0 + tx * 8;
        *(float4*)cr       = make_float4(r[0], r[1], r[2], r[3]);
        *(float4*)(cr + 4) = make_float4(r[4], r[5], r[6], r[7]);
    }
}

// ---------------- launch ----------------------------------------------------
extern "C" void kernel_launch(void* const* d_in, const int* in_sizes, int n_in,
                              void* d_out, int out_size)
{
    const float* query = (const float*)d_in[0];
    const float* key   = (const float*)d_in[1];
    const float* value = (const float*)d_in[2];
    const float* mask  = (const float*)d_in[3];
    const float* Wq    = (const float*)d_in[4];
    const float* Wke   = (const float*)d_in[5];
    const float* Wkr   = (const float*)d_in[6];
    const float* Wv    = (const float*)d_in[7];
    const float* Wf    = (const float*)d_in[8];
    const float* u_p   = (const float*)d_in[9];
    const float* v_p   = (const float*)d_in[10];

    float* out  = (float*)d_out;                       // (1,2048,1024)
    float* Wt   = out + (long long)SQ * DM;            // (1,16,2048,2048)
    float* loss = Wt + (long long)NH * SS;             // scalar

    float *fq, *fk, *fv, *frel, *fqrel, *fqv, *fbhat;
    cudaGetSymbolAddress((void**)&fq,    g_q);
    cudaGetSymbolAddress((void**)&fk,    g_k);
    cudaGetSymbolAddress((void**)&fv,    g_v);
    cudaGetSymbolAddress((void**)&frel,  g_rel);
    cudaGetSymbolAddress((void**)&fqrel, g_qrel);
    cudaGetSymbolAddress((void**)&fqv,   g_qv);
    cudaGetSymbolAddress((void**)&fbhat, g_bhat);

    init_kernel<<<1, 32>>>();
    relenc_kernel<<<(SQ * DM) / 256, 256>>>();

    dim3 gP(DM / 128, SQ / 128);
    sgemm_tn_kernel<<<gP, 256>>>(query, Wq,  fq,    DM, DM, DM, DM, 0, 0, 0);
    sgemm_tn_kernel<<<gP, 256>>>(key,   Wke, fk,    DM, DM, DM, DM, 0, 0, 0);
    sgemm_tn_kernel<<<gP, 256>>>(value, Wv,  fv,    DM, DM, DM, DM, 0, 0, 0);
    sgemm_tn_kernel<<<gP, 256>>>(frel,  Wkr, fqrel, DM, DM, DM, DM, 0, 0, 0);

    addbias_kernel<<<(SQ * DM) / 256, 256>>>(u_p, v_p);

    dim3 gB(SQ / 128, SQ / 128, NH);
    // B_D_hat[h] = (q+v)_h @ (rel_enc @ Wkr^T)_h^T
    sgemm_tn_kernel<<<gB, 256>>>(fqv, fqrel, fbhat, 64, DM, DM, SQ, 64, 64, SS);
    score_kernel<<<gB, 256>>>(mask, Wt);
    softmax_kernel<<<dim3(SQ, NH), 256>>>(Wt);
    loss_kernel<<<1, 32>>>(loss);
    av_kernel<<<dim3(1, SQ / 128, NH), 256>>>(Wt);

    dim3 gF(DM / 128, SQ / 128);
    final_kernel<<<gF, 256>>>(Wf, out);
}